// round 2
// baseline (speedup 1.0000x reference)
#include <cuda_runtime.h>
#include <math.h>

// Problem constants
#define H_IN   192
#define W_IN   192
#define HOUT   96
#define WOUT   96
#define C1     32
#define NNODES 17
#define BATCH  128

// Tiling
#define TILE   16          // output tile (16x16)
#define HT     18          // h tile dim (TILE + 2 halo)
#define INT_   37          // input tile dim (2*16 + 2 + 3)
#define INP    40          // padded input row stride in smem

#define SMEM_IN  (INT_*INP)          // 1480 floats
#define SMEM_H   (C1*HT*HT)          // 10368 floats
#define SMEM_W2  (9*C1*NNODES)       // 4896 floats
#define SMEM_FLOATS (SMEM_IN + SMEM_H + SMEM_W2)
#define SMEM_BYTES  (SMEM_FLOATS * 4)

__constant__ float cW1[9*C1];    // [ky*3+kx][c]
__constant__ float cB1[C1];
__constant__ float cB2[NNODES];

// scratch: confidence maps in (B, N, H, W) layout
__device__ float g_cms[BATCH*NNODES*HOUT*WOUT];

__global__ __launch_bounds__(256, 3)
void conv_fused_kernel(const float* __restrict__ crops,
                       const float* __restrict__ W2g)
{
    extern __shared__ float sm[];
    float* s_in = sm;                     // [INT_][INP]
    float* s_h  = sm + SMEM_IN;           // [C1][HT][HT]
    float* s_w2 = sm + SMEM_IN + SMEM_H;  // [9][C1][NNODES]

    const int tid = threadIdx.x;
    const int x0 = blockIdx.x * TILE;
    const int y0 = blockIdx.y * TILE;
    const int b  = blockIdx.z;

    // stage W2 into smem (coalesced)
    for (int i = tid; i < SMEM_W2; i += 256) s_w2[i] = W2g[i];

    // stage input tile: input row = 2*y0 - 2 + r  (r = 2*ly + ky, ly in [0,18), ky in [0,3))
    const float* img = crops + (size_t)b * H_IN * W_IN;
    for (int i = tid; i < INT_*INT_; i += 256) {
        int r  = i / INT_;
        int cc = i - r * INT_;
        int iy = 2*y0 - 2 + r;
        int ix = 2*x0 - 2 + cc;
        float v = 0.0f;
        if (iy >= 0 && iy < H_IN && ix >= 0 && ix < W_IN)
            v = img[iy * W_IN + ix];
        s_in[r * INP + cc] = v;
    }
    __syncthreads();

    // conv1 (stride 2, pad_lo=0): h[hy][hx][c] = relu(b1 + sum_{ky,kx} in[2hy+ky][2hx+kx]*W1)
    // h tile covers global hy = y0-1+ly ; values outside [0,96) must be ZERO (conv2 SAME pad).
    for (int p = tid; p < HT*HT; p += 256) {
        int ly = p / HT;
        int lx = p - ly * HT;
        int gy = y0 - 1 + ly;
        int gx = x0 - 1 + lx;
        bool valid = (gy >= 0) && (gy < HOUT) && (gx >= 0) && (gx < WOUT);

        float in9[9];
        #pragma unroll
        for (int ky = 0; ky < 3; ky++)
            #pragma unroll
            for (int kx = 0; kx < 3; kx++)
                in9[ky*3+kx] = s_in[(2*ly + ky) * INP + (2*lx + kx)];

        #pragma unroll
        for (int c = 0; c < C1; c++) {
            float acc = cB1[c];
            #pragma unroll
            for (int k = 0; k < 9; k++)
                acc = fmaf(in9[k], cW1[k*C1 + c], acc);
            acc = fmaxf(acc, 0.0f);
            s_h[c * (HT*HT) + p] = valid ? acc : 0.0f;
        }
    }
    __syncthreads();

    // conv2 (stride 1, pad 1): out[y][x][n] = b2 + sum_{c,dy,dx} h[y-1+dy][x-1+dx][c]*W2
    const int ty = tid >> 4;
    const int tx = tid & 15;

    float acc[NNODES];
    #pragma unroll
    for (int n = 0; n < NNODES; n++) acc[n] = cB2[n];

    #pragma unroll 1
    for (int c = 0; c < C1; c++) {
        const float* hc = s_h + c * (HT*HT);
        #pragma unroll
        for (int dy = 0; dy < 3; dy++) {
            const float* hrow = hc + (ty + dy) * HT + tx;
            float h0 = hrow[0];
            float h1 = hrow[1];
            float h2 = hrow[2];
            const float* wbase = s_w2 + ((dy*3) * C1 + c) * NNODES;
            #pragma unroll
            for (int n = 0; n < NNODES; n++)
                acc[n] = fmaf(h0, wbase[n], acc[n]);
            wbase += C1 * NNODES;
            #pragma unroll
            for (int n = 0; n < NNODES; n++)
                acc[n] = fmaf(h1, wbase[n], acc[n]);
            wbase += C1 * NNODES;
            #pragma unroll
            for (int n = 0; n < NNODES; n++)
                acc[n] = fmaf(h2, wbase[n], acc[n]);
        }
    }

    const int y = y0 + ty;
    const int x = x0 + tx;
    float* outb = g_cms + (size_t)b * NNODES * HOUT * WOUT + (size_t)y * WOUT + x;
    #pragma unroll
    for (int n = 0; n < NNODES; n++)
        outb[(size_t)n * HOUT * WOUT] = acc[n];
}

// one block per (b, n): argmax over 96*96 with first-index tie-break, then refine
__global__ void peaks_kernel(float* __restrict__ out)
{
    const int bn = blockIdx.x;                 // b*17 + n
    const float* cm = g_cms + (size_t)bn * HOUT * WOUT;
    const int tid = threadIdx.x;

    float best = -INFINITY;
    int bidx = 0;
    for (int i = tid; i < HOUT*WOUT; i += 256) {
        float v = cm[i];
        if (v > best) { best = v; bidx = i; }
    }

    __shared__ float sv[256];
    __shared__ int   si[256];
    sv[tid] = best; si[tid] = bidx;
    __syncthreads();
    for (int s = 128; s > 0; s >>= 1) {
        if (tid < s) {
            float ov = sv[tid + s]; int oi = si[tid + s];
            if (ov > sv[tid] || (ov == sv[tid] && oi < si[tid])) {
                sv[tid] = ov; si[tid] = oi;
            }
        }
        __syncthreads();
    }

    if (tid == 0) {
        float val = sv[0];
        int idx = si[0];
        int yi = idx / WOUT;
        int xi = idx - yi * WOUT;

        auto g = [&](int yy, int xx) -> float {
            yy = max(0, min(HOUT-1, yy));
            xx = max(0, min(WOUT-1, xx));
            return cm[yy * WOUT + xx];
        };
        float ddx = g(yi, xi+1) - g(yi, xi-1);
        float ddy = g(yi+1, xi) - g(yi-1, xi);
        float sx = (ddx > 0.0f) ? 1.0f : ((ddx < 0.0f) ? -1.0f : 0.0f);
        float sy = (ddy > 0.0f) ? 1.0f : ((ddy < 0.0f) ? -1.0f : 0.0f);

        float px = ((float)xi + 0.25f * sx) * 2.0f;
        float py = ((float)yi + 0.25f * sy) * 2.0f;
        if (!(val >= 0.2f)) { px = nanf(""); py = nanf(""); }

        out[bn*3 + 0] = px;
        out[bn*3 + 1] = py;
        out[bn*3 + 2] = val;
    }
}

extern "C" void kernel_launch(void* const* d_in, const int* in_sizes, int n_in,
                              void* d_out, int out_size)
{
    const float* crops = (const float*)d_in[0];
    const float* W1    = (const float*)d_in[1];
    const float* b1    = (const float*)d_in[2];
    const float* W2    = (const float*)d_in[3];
    const float* b2    = (const float*)d_in[4];
    float* out = (float*)d_out;

    cudaMemcpyToSymbolAsync(cW1, W1, 9*C1*sizeof(float), 0, cudaMemcpyDeviceToDevice, 0);
    cudaMemcpyToSymbolAsync(cB1, b1, C1*sizeof(float), 0, cudaMemcpyDeviceToDevice, 0);
    cudaMemcpyToSymbolAsync(cB2, b2, NNODES*sizeof(float), 0, cudaMemcpyDeviceToDevice, 0);

    cudaFuncSetAttribute(conv_fused_kernel,
                         cudaFuncAttributeMaxDynamicSharedMemorySize, SMEM_BYTES);

    dim3 grid(WOUT/TILE, HOUT/TILE, BATCH);
    conv_fused_kernel<<<grid, 256, SMEM_BYTES>>>(crops, W2);

    peaks_kernel<<<BATCH*NNODES, 256>>>(out);
}